// round 8
// baseline (speedup 1.0000x reference)
#include <cuda_runtime.h>
#include <cuda_bf16.h>
#include <math.h>

#define NN 4096
#define C 7
#define MAXDEG 96
#define HASH 1024
#define WPB 8                // warps per wedge block
#define WGRID (NN / WPB)     // 512 wedge blocks
#define SIG1 0.731058578630004896f   // sigmoid(1)

// ---- static device scratch (zero at load; self-cleaning across replays) ----
__device__ int    g_deg[NN];
__device__ int    g_info[NN];         // label | mask<<3 | diag<<4
__device__ float  g_endp[NN];         // exp(-preds[p, l_p])
__device__ float  g_eP[NN * C];       // exp(preds[q, i])
__device__ float  g_vtab[(MAXDEG + 1) * (MAXDEG + 1)];  // v(sub, inter)
__device__ int    g_nbr[NN * MAXDEG];
__device__ double g_dcc[C * C];
__device__ int    g_hi[C * C];
__device__ int    g_hs[C * C];
__device__ int    g_N[C];
__device__ float  g_T[C * C];
__device__ float  g_U[C];
__device__ double g_ce;
__device__ unsigned int g_ticket;     // wraps via atomicInc -> replay safe

__device__ __forceinline__ float vfun(float sub, float inter) {
    float r = (1.0f + SIG1 * sub) / (1.0f + SIG1 * inter);
    return 1.0f / (1.0f + expf(r));
}

// hash-table insert: key bits[0:13), mark bit 13, count bits[14:32)
__device__ __forceinline__ void hins(unsigned* tb, int q, unsigned addv, bool isOr) {
    unsigned key = (unsigned)q + 1u;
    int h = q & (HASH - 1);
    while (true) {
        unsigned cur = tb[h];
        unsigned k = cur & 0x1FFFu;
        if (k == key) break;
        if (k == 0u) {
            unsigned prev = atomicCAS(&tb[h], 0u, key);
            if (prev == 0u || (prev & 0x1FFFu) == key) break;
        }
        h = (h + 1) & (HASH - 1);
    }
    if (isOr) atomicOr(&tb[h], addv);
    else      atomicAdd(&tb[h], addv);
}

// ---- build: rows + degree + per-node precompute; block 0: g_N + vtab ----
__global__ void k_build(const int* __restrict__ adj,
                        const float* __restrict__ preds,
                        const int* __restrict__ labels,
                        const int* __restrict__ mask) {
    int p = blockIdx.x, t = threadIdx.x;
    __shared__ int cnt, diag;
    __shared__ int sN[C];

    if (p == 0) {
        if (t < C) sN[t] = 0;
        __syncthreads();
        int c0=0,c1=0,c2=0,c3=0,c4=0,c5=0,c6=0;
        for (int i = t; i < NN; i += blockDim.x) {
            if (mask[i]) {
                int l = labels[i];
                c0 += (l==0); c1 += (l==1); c2 += (l==2); c3 += (l==3);
                c4 += (l==4); c5 += (l==5); c6 += (l==6);
            }
        }
        if (c0) atomicAdd(&sN[0], c0);
        if (c1) atomicAdd(&sN[1], c1);
        if (c2) atomicAdd(&sN[2], c2);
        if (c3) atomicAdd(&sN[3], c3);
        if (c4) atomicAdd(&sN[4], c4);
        if (c5) atomicAdd(&sN[5], c5);
        if (c6) atomicAdd(&sN[6], c6);
        // v(sub, inter) lookup table
        for (int i = t; i < (MAXDEG + 1) * (MAXDEG + 1); i += blockDim.x)
            g_vtab[i] = vfun((float)(i / (MAXDEG + 1)), (float)(i % (MAXDEG + 1)));
        __syncthreads();
        if (t < C) g_N[t] = sN[t];
    }

    if (t == 0) { cnt = 0; diag = 0; }
    __syncthreads();
    const int4* row = (const int4*)(adj + (size_t)p * NN);
    for (int qb = t; qb < NN / 4; qb += blockDim.x) {
        int4 v = row[qb];
        if ((v.x | v.y | v.z | v.w) == 0) continue;   // 98% of quads
        int q = qb * 4;
        if (v.x) { int s = atomicAdd(&cnt, 1); if (s < MAXDEG) g_nbr[p * MAXDEG + s] = q;     if (q     == p) diag = 1; }
        if (v.y) { int s = atomicAdd(&cnt, 1); if (s < MAXDEG) g_nbr[p * MAXDEG + s] = q + 1; if (q + 1 == p) diag = 1; }
        if (v.z) { int s = atomicAdd(&cnt, 1); if (s < MAXDEG) g_nbr[p * MAXDEG + s] = q + 2; if (q + 2 == p) diag = 1; }
        if (v.w) { int s = atomicAdd(&cnt, 1); if (s < MAXDEG) g_nbr[p * MAXDEG + s] = q + 3; if (q + 3 == p) diag = 1; }
    }
    __syncthreads();
    if (t == 0) {
        int degp = (cnt < MAXDEG) ? cnt : MAXDEG;
        g_deg[p]  = degp;
        int mp = mask[p];
        int lp = labels[p];
        g_info[p] = lp | (mp ? 8 : 0) | (diag ? 16 : 0);

        const float* r = preds + p * C;
        float v0 = r[0], v1 = r[1], v2 = r[2], v3 = r[3], v4 = r[4], v5 = r[5], v6 = r[6];
        float rl = r[lp];
        float mx = fmaxf(fmaxf(fmaxf(v0, v1), fmaxf(v2, v3)), fmaxf(fmaxf(v4, v5), v6));
        float e0 = expf(v0-mx), e1 = expf(v1-mx), e2 = expf(v2-mx), e3 = expf(v3-mx);
        float e4 = expf(v4-mx), e5 = expf(v5-mx), e6 = expf(v6-mx);
        float se = e0+e1+e2+e3+e4+e5+e6;
        atomicAdd(&g_ce, (double)(rl - (mx + logf(se))));
        float emx = expf(mx);
        float p0 = e0*emx, p1 = e1*emx, p2 = e2*emx, p3 = e3*emx,
              p4 = e4*emx, p5 = e5*emx, p6 = e6*emx;
        float* eP = g_eP + p * C;
        eP[0]=p0; eP[1]=p1; eP[2]=p2; eP[3]=p3; eP[4]=p4; eP[5]=p5; eP[6]=p6;
        float endp = expf(-rl);
        g_endp[p] = endp;
        if (mp) {
            atomicAdd(&g_T[0*C+lp], p0);
            atomicAdd(&g_T[1*C+lp], p1);
            atomicAdd(&g_T[2*C+lp], p2);
            atomicAdd(&g_T[3*C+lp], p3);
            atomicAdd(&g_T[4*C+lp], p4);
            atomicAdd(&g_T[5*C+lp], p5);
            atomicAdd(&g_T[6*C+lp], p6);
            atomicAdd(&g_U[lp], endp * vfun((float)degp, 0.0f));
        }
    }
}

// ---- wedge: warp-per-node, hash table, table-driven math ----
__global__ void __launch_bounds__(256)
k_wedge(const int* __restrict__ mask,
        float* __restrict__ out) {
    __shared__ unsigned tab[WPB * HASH];
    __shared__ float sdccw[WPB][C];
    __shared__ int   szcw[WPB][C];
    __shared__ int   shiw[WPB];

    int wid = threadIdx.x >> 5, lane = threadIdx.x & 31;
    int p = blockIdx.x * WPB + wid;
    unsigned* tb = tab + wid * HASH;

    int degp = g_deg[p];
    int infop = g_info[p];
    int lp = infop & 7;

    if ((infop & 8) && degp > 0) {
        uint4* t4 = (uint4*)tb;
        #pragma unroll
        for (int i = lane; i < HASH / 4; i += 32) t4[i] = make_uint4(0u,0u,0u,0u);
        if (lane < C) { sdccw[wid][lane] = 0.0f; szcw[wid][lane] = 0; }
        if (lane == 0) shiw[wid] = 0;
        __syncwarp();

        const int* np = g_nbr + p * MAXDEG;
        for (int base = 0; base < degp; base += 32) {
            int nrem = min(32, degp - base);
            int myk  = (lane < nrem) ? np[base + lane] : 0;
            int mydk = (lane < nrem) ? g_deg[myk] : 0;
            for (int a = 0; a < nrem; a++) {
                int k  = __shfl_sync(0xFFFFFFFFu, myk,  a);
                int dk = __shfl_sync(0xFFFFFFFFu, mydk, a);
                const int* nk = g_nbr + k * MAXDEG;
                for (int b = lane; b < dk; b += 32)
                    hins(tb, nk[b], 1u << 14, false);       // inter += 1
            }
            if (lane < nrem) hins(tb, myk, 1u << 13, true); // neighbor mark
        }
        __syncwarp();

        float endp = g_endp[p];
        float v0   = g_vtab[degp * (MAXDEG + 1)];           // v(degp, 0)
        for (int s = lane; s < HASH; s += 32) {
            unsigned w = tb[s];
            unsigned key = w & 0x1FFFu;
            if (!key) continue;
            int q = (int)key - 1;
            int inter = (int)(w >> 14);
            int info = g_info[q];
            if (!(info & 8)) continue;                      // mask[q]
            int corr = (int)((w >> 13) & 1u) & (~(info >> 4) & 1);
            if ((inter | corr) == 0) continue;
            int lq = info & 7;
            int sub = degp - inter - corr;
            if (inter > 0) atomicOr(&shiw[wid], 1 << lq);
            if (sub == 0)  atomicAdd(&szcw[wid][lq], 1);
            if (lq != lp) {
                float d = endp * g_eP[q * C + lp] *
                          (g_vtab[sub * (MAXDEG + 1) + inter] - v0);
                atomicAdd(&sdccw[wid][lq], d);
            }
        }
        __syncwarp();
        if (lane < C) {
            int j = lane;
            float d = sdccw[wid][j];
            if (d != 0.0f) atomicAdd(&g_dcc[lp * C + j], (double)d);
            if ((shiw[wid] >> j) & 1) g_hi[lp * C + j] = 1;
            if (szcw[wid][j] < g_N[j]) g_hs[lp * C + j] = 1;
        }
    }

    // ---- last block combines, then resets accumulators ----
    __syncthreads();
    __threadfence();
    if (threadIdx.x == 0) {
        unsigned tk = atomicInc(&g_ticket, WGRID - 1);
        if (tk == WGRID - 1) {
            double tot = 0.0;
            for (int i = 0; i < C; i++) {
                double inv_i = (g_N[i] > 0) ? 1.0 / (double)g_N[i] : 0.0;
                for (int j = 0; j < C; j++) {
                    if (i == j) continue;
                    if (g_hs[i * C + j] && g_hi[i * C + j]) {
                        double inv_j = (g_N[j] > 0) ? 1.0 / (double)g_N[j] : 0.0;
                        tot += inv_i * inv_j *
                               ((double)g_U[i] * (double)g_T[i * C + j] + g_dcc[i * C + j]);
                    }
                }
            }
            out[0] = (float)(-(g_ce / (double)NN) + 0.001 * tot);
            for (int i = 0; i < C * C; i++) {
                g_dcc[i] = 0.0; g_hi[i] = 0; g_hs[i] = 0; g_T[i] = 0.0f;
            }
            for (int i = 0; i < C; i++) g_U[i] = 0.0f;
            g_ce = 0.0;
        }
    }
}

extern "C" void kernel_launch(void* const* d_in, const int* in_sizes, int n_in,
                              void* d_out, int out_size) {
    const float* preds  = (const float*)d_in[0];
    const int*   labels = (const int*)d_in[1];
    const int*   mask   = (const int*)d_in[2];
    const int*   adj    = (const int*)d_in[3];
    float* out = (float*)d_out;

    k_build<<<NN, 256>>>(adj, preds, labels, mask);
    k_wedge<<<WGRID, 256>>>(mask, out);
}

// round 9
// speedup vs baseline: 1.4091x; 1.4091x over previous
#include <cuda_runtime.h>
#include <cuda_bf16.h>
#include <math.h>

#define NN 4096
#define C 7
#define MAXDEG 96
#define VT (MAXDEG + 1)
#define SIG1 0.731058578630004896f   // sigmoid(1)

// ---- static device scratch (zero at load; self-cleaning across replays) ----
__device__ int    g_deg[NN];
__device__ int    g_info[NN];         // label | mask<<3 | diag<<4
__device__ float  g_endp[NN];         // exp(-preds[p, l_p])
__device__ float  g_eP[NN * C];       // exp(preds[q, i])
__device__ float  g_vtab[VT * VT];    // v(sub, inter)
__device__ int    g_nbr[NN * MAXDEG];
__device__ double g_dcc[C * C];
__device__ int    g_hi[C * C];
__device__ int    g_hs[C * C];
__device__ int    g_N[C];
__device__ float  g_T[C * C];
__device__ float  g_U[C];
__device__ double g_ce;
__device__ unsigned int g_ticket;     // wraps via atomicInc -> replay safe

__device__ __forceinline__ float vfun(float sub, float inter) {
    float r = (1.0f + SIG1 * sub) / (1.0f + SIG1 * inter);
    return 1.0f / (1.0f + expf(r));
}

// ---- build: rows + degree + per-node precompute; block 0: g_N + vtab ----
__global__ void k_build(const int* __restrict__ adj,
                        const float* __restrict__ preds,
                        const int* __restrict__ labels,
                        const int* __restrict__ mask) {
    int p = blockIdx.x, t = threadIdx.x;
    __shared__ int cnt, diag;
    __shared__ int sN[C];

    if (p == 0) {
        if (t < C) sN[t] = 0;
        __syncthreads();
        int c0=0,c1=0,c2=0,c3=0,c4=0,c5=0,c6=0;
        for (int i = t; i < NN; i += blockDim.x) {
            if (mask[i]) {
                int l = labels[i];
                c0 += (l==0); c1 += (l==1); c2 += (l==2); c3 += (l==3);
                c4 += (l==4); c5 += (l==5); c6 += (l==6);
            }
        }
        if (c0) atomicAdd(&sN[0], c0);
        if (c1) atomicAdd(&sN[1], c1);
        if (c2) atomicAdd(&sN[2], c2);
        if (c3) atomicAdd(&sN[3], c3);
        if (c4) atomicAdd(&sN[4], c4);
        if (c5) atomicAdd(&sN[5], c5);
        if (c6) atomicAdd(&sN[6], c6);
        for (int i = t; i < VT * VT; i += blockDim.x)
            g_vtab[i] = vfun((float)(i / VT), (float)(i % VT));
        __syncthreads();
        if (t < C) g_N[t] = sN[t];
    }

    if (t == 0) { cnt = 0; diag = 0; }
    __syncthreads();
    const int4* row = (const int4*)(adj + (size_t)p * NN);
    for (int qb = t; qb < NN / 4; qb += blockDim.x) {
        int4 v = row[qb];
        if ((v.x | v.y | v.z | v.w) == 0) continue;   // ~98% of quads
        int q = qb * 4;
        if (v.x) { int s = atomicAdd(&cnt, 1); if (s < MAXDEG) g_nbr[p * MAXDEG + s] = q;     if (q     == p) diag = 1; }
        if (v.y) { int s = atomicAdd(&cnt, 1); if (s < MAXDEG) g_nbr[p * MAXDEG + s] = q + 1; if (q + 1 == p) diag = 1; }
        if (v.z) { int s = atomicAdd(&cnt, 1); if (s < MAXDEG) g_nbr[p * MAXDEG + s] = q + 2; if (q + 2 == p) diag = 1; }
        if (v.w) { int s = atomicAdd(&cnt, 1); if (s < MAXDEG) g_nbr[p * MAXDEG + s] = q + 3; if (q + 3 == p) diag = 1; }
    }
    __syncthreads();
    if (t == 0) {
        int degp = (cnt < MAXDEG) ? cnt : MAXDEG;
        g_deg[p]  = degp;
        int mp = mask[p];
        int lp = labels[p];
        g_info[p] = lp | (mp ? 8 : 0) | (diag ? 16 : 0);

        const float* r = preds + p * C;
        float v0 = r[0], v1 = r[1], v2 = r[2], v3 = r[3], v4 = r[4], v5 = r[5], v6 = r[6];
        float rl = r[lp];
        float mx = fmaxf(fmaxf(fmaxf(v0, v1), fmaxf(v2, v3)), fmaxf(fmaxf(v4, v5), v6));
        float e0 = expf(v0-mx), e1 = expf(v1-mx), e2 = expf(v2-mx), e3 = expf(v3-mx);
        float e4 = expf(v4-mx), e5 = expf(v5-mx), e6 = expf(v6-mx);
        float se = e0+e1+e2+e3+e4+e5+e6;
        atomicAdd(&g_ce, (double)(rl - (mx + logf(se))));
        float emx = expf(mx);
        float p0 = e0*emx, p1 = e1*emx, p2 = e2*emx, p3 = e3*emx,
              p4 = e4*emx, p5 = e5*emx, p6 = e6*emx;
        float* eP = g_eP + p * C;
        eP[0]=p0; eP[1]=p1; eP[2]=p2; eP[3]=p3; eP[4]=p4; eP[5]=p5; eP[6]=p6;
        float endp = expf(-rl);
        g_endp[p] = endp;
        if (mp) {
            atomicAdd(&g_T[0*C+lp], p0);
            atomicAdd(&g_T[1*C+lp], p1);
            atomicAdd(&g_T[2*C+lp], p2);
            atomicAdd(&g_T[3*C+lp], p3);
            atomicAdd(&g_T[4*C+lp], p4);
            atomicAdd(&g_T[5*C+lp], p5);
            atomicAdd(&g_T[6*C+lp], p6);
            atomicAdd(&g_U[lp], endp * vfun((float)degp, 0.0f));
        }
    }
}

// ---- wedge: block-per-node, packed dense counters, no list, table math ----
__global__ void __launch_bounds__(128, 16)
k_wedge(float* __restrict__ out) {
    __shared__ unsigned cnt[NN / 2];   // two 16b lanes/word: bits0-14 inter, bit15 nbr mark
    __shared__ float sdcc[C];
    __shared__ int   shi[C], szc[C];

    int p = blockIdx.x, t = threadIdx.x;
    int infop = g_info[p];
    int degp  = g_deg[p];
    int lp    = infop & 7;

    if ((infop & 8) && degp > 0) {
        uint4* c4 = (uint4*)cnt;
        #pragma unroll
        for (int i = t; i < NN / 8; i += 128) c4[i] = make_uint4(0u, 0u, 0u, 0u);
        if (t < C) { sdcc[t] = 0.0f; shi[t] = 0; szc[t] = 0; }
        __syncthreads();

        // phase 1: scatter wedge counts (fire-and-forget atomics, no returns)
        const int* np = g_nbr + p * MAXDEG;
        int wid = t >> 5, lane = t & 31;
        for (int a = wid; a < degp; a += 4) {
            int k = np[a];
            int dk = g_deg[k];
            const int* nk = g_nbr + k * MAXDEG;
            for (int b = lane; b < dk; b += 32) {
                int q = nk[b];
                atomicAdd(&cnt[q >> 1], 1u << ((q & 1) * 16));
            }
        }
        for (int a = t; a < degp; a += 128) {
            int q = np[a];
            atomicOr(&cnt[q >> 1], 0x8000u << ((q & 1) * 16));
        }
        __syncthreads();

        // phase 2: uint4 scan with early-out; table-driven math
        float endp = g_endp[p];
        float v0   = g_vtab[degp * VT];                   // v(degp, 0)
        for (int i = t; i < NN / 8; i += 128) {
            uint4 w4 = c4[i];
            if ((w4.x | w4.y | w4.z | w4.w) == 0u) continue;
            #pragma unroll
            for (int c = 0; c < 4; c++) {
                unsigned word = (c == 0) ? w4.x : (c == 1) ? w4.y : (c == 2) ? w4.z : w4.w;
                if (!word) continue;
                #pragma unroll
                for (int h = 0; h < 2; h++) {
                    unsigned v = (word >> (h * 16)) & 0xFFFFu;
                    if (!v) continue;
                    int q = (i * 4 + c) * 2 + h;
                    int info = g_info[q];
                    if (!(info & 8)) continue;            // mask[q]
                    int inter = (int)(v & 0x7FFFu);
                    int corr  = (int)(v >> 15) & (~(info >> 4) & 1);
                    if ((inter | corr) == 0) continue;
                    int lq = info & 7;
                    int sub = degp - inter - corr;
                    if (inter > 0) shi[lq] = 1;
                    if (sub == 0)  atomicAdd(&szc[lq], 1);
                    if (lq != lp) {
                        float d = endp * g_eP[q * C + lp] *
                                  (g_vtab[sub * VT + inter] - v0);
                        atomicAdd(&sdcc[lq], d);
                    }
                }
            }
        }
        __syncthreads();
        if (t < C) {
            if (sdcc[t] != 0.0f) atomicAdd(&g_dcc[lp * C + t], (double)sdcc[t]);
            if (shi[t]) g_hi[lp * C + t] = 1;
            if (szc[t] < g_N[t]) g_hs[lp * C + t] = 1;    // exists masked label-t q with sub>0
        }
    }

    // ---- last block combines, then resets accumulators ----
    __threadfence();
    if (t == 0) {
        unsigned tk = atomicInc(&g_ticket, NN - 1);
        if (tk == NN - 1) {
            double tot = 0.0;
            for (int i = 0; i < C; i++) {
                double inv_i = (g_N[i] > 0) ? 1.0 / (double)g_N[i] : 0.0;
                for (int j = 0; j < C; j++) {
                    if (i == j) continue;
                    if (g_hs[i * C + j] && g_hi[i * C + j]) {
                        double inv_j = (g_N[j] > 0) ? 1.0 / (double)g_N[j] : 0.0;
                        tot += inv_i * inv_j *
                               ((double)g_U[i] * (double)g_T[i * C + j] + g_dcc[i * C + j]);
                    }
                }
            }
            out[0] = (float)(-(g_ce / (double)NN) + 0.001 * tot);
            for (int i = 0; i < C * C; i++) {
                g_dcc[i] = 0.0; g_hi[i] = 0; g_hs[i] = 0; g_T[i] = 0.0f;
            }
            for (int i = 0; i < C; i++) g_U[i] = 0.0f;
            g_ce = 0.0;
        }
    }
}

extern "C" void kernel_launch(void* const* d_in, const int* in_sizes, int n_in,
                              void* d_out, int out_size) {
    const float* preds  = (const float*)d_in[0];
    const int*   labels = (const int*)d_in[1];
    const int*   mask   = (const int*)d_in[2];
    const int*   adj    = (const int*)d_in[3];
    float* out = (float*)d_out;

    k_build<<<NN, 256>>>(adj, preds, labels, mask);
    k_wedge<<<NN, 128>>>(out);
}

// round 11
// speedup vs baseline: 1.5694x; 1.1138x over previous
#include <cuda_runtime.h>
#include <cuda_bf16.h>
#include <math.h>

#define NN 4096
#define C 7
#define MAXDEG 96
#define VT (MAXDEG + 1)
#define LISTCAP 2048
#define SIG1 0.731058578630004896f   // sigmoid(1)

// ---- static device scratch (zero at load; self-cleaning across replays) ----
__device__ int    g_deg[NN];          // full degree
__device__ int    g_degm[NN];         // masked-neighbor count
__device__ int    g_info[NN];         // label | mask<<3 | diag<<4
__device__ float  g_endp[NN];         // exp(-preds[p, l_p])
__device__ float  g_eP[NN * C];       // exp(preds[q, i])
__device__ float  g_vtab[VT * VT];    // v(sub, inter)
__device__ int    g_nbr[NN * MAXDEG];   // all neighbors
__device__ int    g_nbrm[NN * MAXDEG];  // masked neighbors only
__device__ double g_dcc[C * C];
__device__ int    g_hi[C * C];
__device__ int    g_hs[C * C];
__device__ int    g_N[C];
__device__ float  g_T[C * C];
__device__ float  g_U[C];
__device__ double g_ce;
__device__ unsigned int g_ticket;     // wraps via atomicInc -> replay safe

__device__ __forceinline__ float vfun(float sub, float inter) {
    float r = (1.0f + SIG1 * sub) / (1.0f + SIG1 * inter);
    return 1.0f / (1.0f + expf(r));
}

// ---- build: lists (full + masked) + per-node precompute; block 0: g_N + vtab ----
__global__ void k_build(const int* __restrict__ adj,
                        const float* __restrict__ preds,
                        const int* __restrict__ labels,
                        const int* __restrict__ mask) {
    int p = blockIdx.x, t = threadIdx.x;
    __shared__ int cnt, cntm, diag;
    __shared__ int sN[C];

    if (p == 0) {
        if (t < C) sN[t] = 0;
        __syncthreads();
        int c0=0,c1=0,c2=0,c3=0,c4=0,c5=0,c6=0;
        for (int i = t; i < NN; i += blockDim.x) {
            if (mask[i]) {
                int l = labels[i];
                c0 += (l==0); c1 += (l==1); c2 += (l==2); c3 += (l==3);
                c4 += (l==4); c5 += (l==5); c6 += (l==6);
            }
        }
        if (c0) atomicAdd(&sN[0], c0);
        if (c1) atomicAdd(&sN[1], c1);
        if (c2) atomicAdd(&sN[2], c2);
        if (c3) atomicAdd(&sN[3], c3);
        if (c4) atomicAdd(&sN[4], c4);
        if (c5) atomicAdd(&sN[5], c5);
        if (c6) atomicAdd(&sN[6], c6);
        for (int i = t; i < VT * VT; i += blockDim.x)
            g_vtab[i] = vfun((float)(i / VT), (float)(i % VT));
        __syncthreads();
        if (t < C) g_N[t] = sN[t];
    }

    if (t == 0) { cnt = 0; cntm = 0; diag = 0; }
    __syncthreads();
    const int4* row = (const int4*)(adj + (size_t)p * NN);
    // front-batched loads (MLP 4), then predicated processing
    int4 v[4];
    #pragma unroll
    for (int j = 0; j < 4; j++) v[j] = row[t + j * 256];
    #pragma unroll
    for (int j = 0; j < 4; j++) {
        if ((v[j].x | v[j].y | v[j].z | v[j].w) == 0) continue;   // ~98% of quads
        int q = (t + j * 256) * 4;
        #pragma unroll
        for (int e = 0; e < 4; e++) {
            int bit = (e == 0) ? v[j].x : (e == 1) ? v[j].y : (e == 2) ? v[j].z : v[j].w;
            if (bit) {
                int qq = q + e;
                int s = atomicAdd(&cnt, 1);
                if (s < MAXDEG) g_nbr[p * MAXDEG + s] = qq;
                if (mask[qq]) {
                    int sm = atomicAdd(&cntm, 1);
                    if (sm < MAXDEG) g_nbrm[p * MAXDEG + sm] = qq;
                }
                if (qq == p) diag = 1;
            }
        }
    }
    __syncthreads();
    if (t == 0) {
        int degp = (cnt < MAXDEG) ? cnt : MAXDEG;
        g_deg[p]  = degp;
        g_degm[p] = (cntm < MAXDEG) ? cntm : MAXDEG;
        int mp = mask[p];
        int lp = labels[p];
        g_info[p] = lp | (mp ? 8 : 0) | (diag ? 16 : 0);

        const float* r = preds + p * C;
        float v0 = r[0], v1 = r[1], v2 = r[2], v3 = r[3], v4 = r[4], v5 = r[5], v6 = r[6];
        float rl = r[lp];
        float mx = fmaxf(fmaxf(fmaxf(v0, v1), fmaxf(v2, v3)), fmaxf(fmaxf(v4, v5), v6));
        float e0 = expf(v0-mx), e1 = expf(v1-mx), e2 = expf(v2-mx), e3 = expf(v3-mx);
        float e4 = expf(v4-mx), e5 = expf(v5-mx), e6 = expf(v6-mx);
        float se = e0+e1+e2+e3+e4+e5+e6;
        atomicAdd(&g_ce, (double)(rl - (mx + logf(se))));
        float emx = expf(mx);
        float p0 = e0*emx, p1 = e1*emx, p2 = e2*emx, p3 = e3*emx,
              p4 = e4*emx, p5 = e5*emx, p6 = e6*emx;
        float* eP = g_eP + p * C;
        eP[0]=p0; eP[1]=p1; eP[2]=p2; eP[3]=p3; eP[4]=p4; eP[5]=p5; eP[6]=p6;
        float endp = expf(-rl);
        g_endp[p] = endp;
        if (mp) {
            atomicAdd(&g_T[0*C+lp], p0);
            atomicAdd(&g_T[1*C+lp], p1);
            atomicAdd(&g_T[2*C+lp], p2);
            atomicAdd(&g_T[3*C+lp], p3);
            atomicAdd(&g_T[4*C+lp], p4);
            atomicAdd(&g_T[5*C+lp], p5);
            atomicAdd(&g_T[6*C+lp], p6);
            atomicAdd(&g_U[lp], endp * vfun((float)degp, 0.0f));
        }
    }
}

// ---- wedge: block-per-node, masked-only scatter, touched list, table math ----
__global__ void __launch_bounds__(128)
k_wedge(float* __restrict__ out) {
    __shared__ unsigned cnt[NN / 2];   // two 16b lanes/word: bits0-14 inter, bit15 nbr mark
    __shared__ unsigned short lst[LISTCAP];
    __shared__ int   nlist;
    __shared__ float sdcc[C];
    __shared__ int   shi[C], szc[C];

    int p = blockIdx.x, t = threadIdx.x;
    int infop = g_info[p];
    int degp  = g_deg[p];
    int lp    = infop & 7;

    if ((infop & 8) && degp > 0) {
        uint4* c4 = (uint4*)cnt;
        #pragma unroll
        for (int i = t; i < NN / 8; i += 128) c4[i] = make_uint4(0u, 0u, 0u, 0u);
        if (t < C) { sdcc[t] = 0.0f; shi[t] = 0; szc[t] = 0; }
        if (t == 0) nlist = 0;
        __syncthreads();

        // phase 1: scatter wedge counts to MASKED q only
        const int* np = g_nbr + p * MAXDEG;
        int wid = t >> 5, lane = t & 31;
        for (int a = wid; a < degp; a += 4) {
            int k = np[a];
            int dmk = g_degm[k];
            const int* nk = g_nbrm + k * MAXDEG;
            for (int b = lane; b < dmk; b += 32) {
                int q = nk[b];
                int sh = (q & 1) * 16;
                unsigned old = atomicAdd(&cnt[q >> 1], 1u << sh);
                if (((old >> sh) & 0xFFFFu) == 0u) {
                    int s = atomicAdd(&nlist, 1);
                    if (s < LISTCAP) lst[s] = (unsigned short)q;
                }
            }
        }
        {   // neighbor marks: masked neighbors of p
            int dmp = g_degm[p];
            const int* npm = g_nbrm + p * MAXDEG;
            for (int a = t; a < dmp; a += 128) {
                int q = npm[a];
                int sh = (q & 1) * 16;
                unsigned old = atomicOr(&cnt[q >> 1], 0x8000u << sh);
                if (((old >> sh) & 0xFFFFu) == 0u) {
                    int s = atomicAdd(&nlist, 1);
                    if (s < LISTCAP) lst[s] = (unsigned short)q;
                }
            }
        }
        __syncthreads();

        // phase 2: touched entries only (all masked by construction)
        float endp = g_endp[p];
        float v0   = g_vtab[degp * VT];                   // v(degp, 0)
        int nl = nlist;
        if (nl <= LISTCAP) {
            for (int ii = t; ii < nl; ii += 128) {
                int q = lst[ii];
                unsigned c = (cnt[q >> 1] >> ((q & 1) * 16)) & 0xFFFFu;
                int info  = g_info[q];
                int inter = (int)(c & 0x7FFFu);
                int corr  = (int)(c >> 15) & (~(info >> 4) & 1);
                if ((inter | corr) == 0) continue;        // marked diag-q only
                int lq = info & 7;
                int sub = degp - inter - corr;
                if (inter > 0) shi[lq] = 1;
                if (sub == 0)  atomicAdd(&szc[lq], 1);
                if (lq != lp) {
                    float d = endp * g_eP[q * C + lp] *
                              (g_vtab[sub * VT + inter] - v0);
                    atomicAdd(&sdcc[lq], d);
                }
            }
        } else {                     // overflow fallback: full packed scan
            for (int i = t; i < NN / 8; i += 128) {
                uint4 w4 = c4[i];
                if ((w4.x | w4.y | w4.z | w4.w) == 0u) continue;
                #pragma unroll
                for (int cc = 0; cc < 4; cc++) {
                    unsigned word = (cc==0)?w4.x:(cc==1)?w4.y:(cc==2)?w4.z:w4.w;
                    if (!word) continue;
                    #pragma unroll
                    for (int h = 0; h < 2; h++) {
                        unsigned v = (word >> (h * 16)) & 0xFFFFu;
                        if (!v) continue;
                        int q = (i * 4 + cc) * 2 + h;
                        int info  = g_info[q];
                        int inter = (int)(v & 0x7FFFu);
                        int corr  = (int)(v >> 15) & (~(info >> 4) & 1);
                        if ((inter | corr) == 0) continue;
                        int lq = info & 7;
                        int sub = degp - inter - corr;
                        if (inter > 0) shi[lq] = 1;
                        if (sub == 0)  atomicAdd(&szc[lq], 1);
                        if (lq != lp) {
                            float d = endp * g_eP[q * C + lp] *
                                      (g_vtab[sub * VT + inter] - v0);
                            atomicAdd(&sdcc[lq], d);
                        }
                    }
                }
            }
        }
        __syncthreads();
        if (t < C) {
            if (sdcc[t] != 0.0f) atomicAdd(&g_dcc[lp * C + t], (double)sdcc[t]);
            if (shi[t]) g_hi[lp * C + t] = 1;
            if (szc[t] < g_N[t]) g_hs[lp * C + t] = 1;    // exists masked label-t q with sub>0
        }
    }

    // ---- last block combines, then resets accumulators ----
    __threadfence();
    if (t == 0) {
        unsigned tk = atomicInc(&g_ticket, NN - 1);
        if (tk == NN - 1) {
            double tot = 0.0;
            for (int i = 0; i < C; i++) {
                double inv_i = (g_N[i] > 0) ? 1.0 / (double)g_N[i] : 0.0;
                for (int j = 0; j < C; j++) {
                    if (i == j) continue;
                    if (g_hs[i * C + j] && g_hi[i * C + j]) {
                        double inv_j = (g_N[j] > 0) ? 1.0 / (double)g_N[j] : 0.0;
                        tot += inv_i * inv_j *
                               ((double)g_U[i] * (double)g_T[i * C + j] + g_dcc[i * C + j]);
                    }
                }
            }
            out[0] = (float)(-(g_ce / (double)NN) + 0.001 * tot);
            for (int i = 0; i < C * C; i++) {
                g_dcc[i] = 0.0; g_hi[i] = 0; g_hs[i] = 0; g_T[i] = 0.0f;
            }
            for (int i = 0; i < C; i++) g_U[i] = 0.0f;
            g_ce = 0.0;
        }
    }
}

extern "C" void kernel_launch(void* const* d_in, const int* in_sizes, int n_in,
                              void* d_out, int out_size) {
    const float* preds  = (const float*)d_in[0];
    const int*   labels = (const int*)d_in[1];
    const int*   mask   = (const int*)d_in[2];
    const int*   adj    = (const int*)d_in[3];
    float* out = (float*)d_out;

    k_build<<<NN, 256>>>(adj, preds, labels, mask);
    k_wedge<<<NN, 128>>>(out);
}

// round 13
// speedup vs baseline: 1.6347x; 1.0416x over previous
#include <cuda_runtime.h>
#include <cuda_bf16.h>
#include <math.h>

#define NN 4096
#define C 7
#define MAXDEG 96
#define VT (MAXDEG + 1)
#define LISTCAP 2048
#define NBLK 1024
#define SIG1 0.731058578630004896f   // sigmoid(1)

// ---- static device scratch (zero at load; self-cleaning across replays) ----
__device__ int    g_deg[NN];          // full degree
__device__ int    g_degm[NN];         // masked-neighbor count
__device__ int    g_info[NN];         // label | mask<<3 | diag<<4
__device__ float  g_endp[NN];         // exp(-preds[p, l_p])
__device__ float  g_eP[NN * C];       // exp(preds[q, i])
__device__ float  g_vtab[VT * VT];    // v(sub, inter)
__device__ int    g_nbr[NN * MAXDEG];   // all neighbors
__device__ int    g_nbrm[NN * MAXDEG];  // masked neighbors only
__device__ int    g_active[NN];       // compacted list of active p
__device__ int    g_nactive;          // count (reset by k_combine)
__device__ double g_dcc[C * C];
__device__ int    g_hi[C * C];
__device__ int    g_hs[C * C];
__device__ int    g_N[C];
__device__ float  g_T[C * C];
__device__ float  g_U[C];
__device__ double g_ce;

__device__ __forceinline__ float vfun(float sub, float inter) {
    float r = (1.0f + SIG1 * sub) / (1.0f + SIG1 * inter);
    return 1.0f / (1.0f + expf(r));
}

// ---- build: lists (full + masked) + per-node precompute; block 0: g_N + vtab ----
__global__ void k_build(const int* __restrict__ adj,
                        const float* __restrict__ preds,
                        const int* __restrict__ labels,
                        const int* __restrict__ mask) {
    int p = blockIdx.x, t = threadIdx.x;
    __shared__ int cnt, cntm, diag;
    __shared__ int sN[C];

    if (p == 0) {
        if (t < C) sN[t] = 0;
        __syncthreads();
        int c0=0,c1=0,c2=0,c3=0,c4=0,c5=0,c6=0;
        for (int i = t; i < NN; i += blockDim.x) {
            if (mask[i]) {
                int l = labels[i];
                c0 += (l==0); c1 += (l==1); c2 += (l==2); c3 += (l==3);
                c4 += (l==4); c5 += (l==5); c6 += (l==6);
            }
        }
        if (c0) atomicAdd(&sN[0], c0);
        if (c1) atomicAdd(&sN[1], c1);
        if (c2) atomicAdd(&sN[2], c2);
        if (c3) atomicAdd(&sN[3], c3);
        if (c4) atomicAdd(&sN[4], c4);
        if (c5) atomicAdd(&sN[5], c5);
        if (c6) atomicAdd(&sN[6], c6);
        for (int i = t; i < VT * VT; i += blockDim.x)
            g_vtab[i] = vfun((float)(i / VT), (float)(i % VT));
        __syncthreads();
        if (t < C) g_N[t] = sN[t];
    }

    if (t == 0) { cnt = 0; cntm = 0; diag = 0; }
    __syncthreads();
    const int4* row = (const int4*)(adj + (size_t)p * NN);
    int4 v[4];
    #pragma unroll
    for (int j = 0; j < 4; j++) v[j] = row[t + j * 256];
    #pragma unroll
    for (int j = 0; j < 4; j++) {
        if ((v[j].x | v[j].y | v[j].z | v[j].w) == 0) continue;   // ~98% of quads
        int q = (t + j * 256) * 4;
        #pragma unroll
        for (int e = 0; e < 4; e++) {
            int bit = (e == 0) ? v[j].x : (e == 1) ? v[j].y : (e == 2) ? v[j].z : v[j].w;
            if (bit) {
                int qq = q + e;
                int s = atomicAdd(&cnt, 1);
                if (s < MAXDEG) g_nbr[p * MAXDEG + s] = qq;
                if (mask[qq]) {
                    int sm = atomicAdd(&cntm, 1);
                    if (sm < MAXDEG) g_nbrm[p * MAXDEG + sm] = qq;
                }
                if (qq == p) diag = 1;
            }
        }
    }
    __syncthreads();
    if (t == 0) {
        int degp = (cnt < MAXDEG) ? cnt : MAXDEG;
        g_deg[p]  = degp;
        g_degm[p] = (cntm < MAXDEG) ? cntm : MAXDEG;
        int mp = mask[p];
        int lp = labels[p];
        g_info[p] = lp | (mp ? 8 : 0) | (diag ? 16 : 0);
        if (mp && degp > 0) {
            int s = atomicAdd(&g_nactive, 1);
            g_active[s] = p;
        }

        const float* r = preds + p * C;
        float v0 = r[0], v1 = r[1], v2 = r[2], v3 = r[3], v4 = r[4], v5 = r[5], v6 = r[6];
        float rl = r[lp];
        float mx = fmaxf(fmaxf(fmaxf(v0, v1), fmaxf(v2, v3)), fmaxf(fmaxf(v4, v5), v6));
        float e0 = expf(v0-mx), e1 = expf(v1-mx), e2 = expf(v2-mx), e3 = expf(v3-mx);
        float e4 = expf(v4-mx), e5 = expf(v5-mx), e6 = expf(v6-mx);
        float se = e0+e1+e2+e3+e4+e5+e6;
        atomicAdd(&g_ce, (double)(rl - (mx + logf(se))));
        float emx = expf(mx);
        float p0 = e0*emx, p1 = e1*emx, p2 = e2*emx, p3 = e3*emx,
              p4 = e4*emx, p5 = e5*emx, p6 = e6*emx;
        float* eP = g_eP + p * C;
        eP[0]=p0; eP[1]=p1; eP[2]=p2; eP[3]=p3; eP[4]=p4; eP[5]=p5; eP[6]=p6;
        float endp = expf(-rl);
        g_endp[p] = endp;
        if (mp) {
            atomicAdd(&g_T[0*C+lp], p0);
            atomicAdd(&g_T[1*C+lp], p1);
            atomicAdd(&g_T[2*C+lp], p2);
            atomicAdd(&g_T[3*C+lp], p3);
            atomicAdd(&g_T[4*C+lp], p4);
            atomicAdd(&g_T[5*C+lp], p5);
            atomicAdd(&g_T[6*C+lp], p6);
            atomicAdd(&g_U[lp], endp * vfun((float)degp, 0.0f));
        }
    }
}

// ---- persistent wedge: active list, counters zeroed once, touched-only rezero ----
__global__ void __launch_bounds__(128)
k_wedge() {
    __shared__ unsigned cnt[NN / 2];   // two 16b lanes/word: bits0-14 inter, bit15 nbr mark
    __shared__ unsigned short lst[LISTCAP];
    __shared__ int   sk[MAXDEG];
    __shared__ int   sdm[MAXDEG];
    __shared__ int   nlist;
    __shared__ float sdcc[C];
    __shared__ int   shi[C], szc[C];

    int t = threadIdx.x;
    uint4* c4 = (uint4*)cnt;
    #pragma unroll
    for (int i = t; i < NN / 8; i += 128) c4[i] = make_uint4(0u, 0u, 0u, 0u);

    int nact = g_nactive;
    int wid = t >> 5, lane = t & 31;

    for (int it = blockIdx.x; it < nact; it += NBLK) {
        int p = g_active[it];
        int degp = g_deg[p];
        int lp   = g_info[p] & 7;

        if (t < C) { sdcc[t] = 0.0f; shi[t] = 0; szc[t] = 0; }
        if (t == 0) nlist = 0;
        // prefetch neighbor ids + masked degrees (parallel, high MLP)
        if (t < degp) {
            int k = g_nbr[p * MAXDEG + t];
            sk[t]  = k;
            sdm[t] = g_degm[k];
        }
        __syncthreads();

        // phase 1: scatter wedge counts to MASKED q only
        for (int a = wid; a < degp; a += 4) {
            int k = sk[a], dmk = sdm[a];
            const int* nk = g_nbrm + k * MAXDEG;
            for (int b = lane; b < dmk; b += 32) {
                int q = nk[b];
                int sh = (q & 1) * 16;
                unsigned old = atomicAdd(&cnt[q >> 1], 1u << sh);
                if (((old >> sh) & 0xFFFFu) == 0u) {
                    int s = atomicAdd(&nlist, 1);
                    if (s < LISTCAP) lst[s] = (unsigned short)q;
                }
            }
        }
        {   // neighbor marks: masked neighbors of p
            int dmp = g_degm[p];
            const int* npm = g_nbrm + p * MAXDEG;
            for (int a = t; a < dmp; a += 128) {
                int q = npm[a];
                int sh = (q & 1) * 16;
                unsigned old = atomicOr(&cnt[q >> 1], 0x8000u << sh);
                if (((old >> sh) & 0xFFFFu) == 0u) {
                    int s = atomicAdd(&nlist, 1);
                    if (s < LISTCAP) lst[s] = (unsigned short)q;
                }
            }
        }
        __syncthreads();

        // phase 2: touched entries only; clear own lane after processing
        float endp = g_endp[p];
        float v0   = g_vtab[degp * VT];                   // v(degp, 0)
        int nl = nlist;
        if (nl <= LISTCAP) {
            for (int ii = t; ii < nl; ii += 128) {
                int q = lst[ii];
                int sh = (q & 1) * 16;
                unsigned c = (cnt[q >> 1] >> sh) & 0xFFFFu;
                atomicAnd(&cnt[q >> 1], ~(0xFFFFu << sh));   // touched-only rezero
                int info  = g_info[q];
                int inter = (int)(c & 0x7FFFu);
                int corr  = (int)(c >> 15) & (~(info >> 4) & 1);
                if ((inter | corr) == 0) continue;           // marked diag-q only
                int lq = info & 7;
                int sub = degp - inter - corr;
                if (inter > 0) shi[lq] = 1;
                if (sub == 0)  atomicAdd(&szc[lq], 1);
                if (lq != lp) {
                    float d = endp * g_eP[q * C + lp] *
                              (g_vtab[sub * VT + inter] - v0);
                    atomicAdd(&sdcc[lq], d);
                }
            }
        } else {                     // overflow fallback: full packed scan + full rezero
            for (int i = t; i < NN / 8; i += 128) {
                uint4 w4 = c4[i];
                if ((w4.x | w4.y | w4.z | w4.w) == 0u) continue;
                c4[i] = make_uint4(0u, 0u, 0u, 0u);
                #pragma unroll
                for (int cc = 0; cc < 4; cc++) {
                    unsigned word = (cc==0)?w4.x:(cc==1)?w4.y:(cc==2)?w4.z:w4.w;
                    if (!word) continue;
                    #pragma unroll
                    for (int h = 0; h < 2; h++) {
                        unsigned v = (word >> (h * 16)) & 0xFFFFu;
                        if (!v) continue;
                        int q = (i * 4 + cc) * 2 + h;
                        int info  = g_info[q];
                        int inter = (int)(v & 0x7FFFu);
                        int corr  = (int)(v >> 15) & (~(info >> 4) & 1);
                        if ((inter | corr) == 0) continue;
                        int lq = info & 7;
                        int sub = degp - inter - corr;
                        if (inter > 0) shi[lq] = 1;
                        if (sub == 0)  atomicAdd(&szc[lq], 1);
                        if (lq != lp) {
                            float d = endp * g_eP[q * C + lp] *
                                      (g_vtab[sub * VT + inter] - v0);
                            atomicAdd(&sdcc[lq], d);
                        }
                    }
                }
            }
        }
        __syncthreads();
        if (t < C) {
            if (sdcc[t] != 0.0f) atomicAdd(&g_dcc[lp * C + t], (double)sdcc[t]);
            if (shi[t]) g_hi[lp * C + t] = 1;
            if (szc[t] < g_N[t]) g_hs[lp * C + t] = 1;    // exists masked label-t q with sub>0
        }
        __syncthreads();   // protect smem state before next iteration
    }
}

// ---- combine: 49 class pairs; then reset accumulators for next replay ----
__global__ void k_combine(float* __restrict__ out) {
    int t = threadIdx.x;
    if (t == 0) {
        double tot = 0.0;
        for (int i = 0; i < C; i++) {
            double inv_i = (g_N[i] > 0) ? 1.0 / (double)g_N[i] : 0.0;
            for (int j = 0; j < C; j++) {
                if (i == j) continue;
                if (g_hs[i * C + j] && g_hi[i * C + j]) {
                    double inv_j = (g_N[j] > 0) ? 1.0 / (double)g_N[j] : 0.0;
                    tot += inv_i * inv_j *
                           ((double)g_U[i] * (double)g_T[i * C + j] + g_dcc[i * C + j]);
                }
            }
        }
        out[0] = (float)(-(g_ce / (double)NN) + 0.001 * tot);
        g_ce = 0.0;
        g_nactive = 0;
    }
    __syncthreads();
    if (t < C * C) { g_dcc[t] = 0.0; g_hi[t] = 0; g_hs[t] = 0; g_T[t] = 0.0f; }
    if (t < C)     g_U[t] = 0.0f;
}

extern "C" void kernel_launch(void* const* d_in, const int* in_sizes, int n_in,
                              void* d_out, int out_size) {
    const float* preds  = (const float*)d_in[0];
    const int*   labels = (const int*)d_in[1];
    const int*   mask   = (const int*)d_in[2];
    const int*   adj    = (const int*)d_in[3];
    float* out = (float*)d_out;

    k_build  <<<NN, 256>>>(adj, preds, labels, mask);
    k_wedge  <<<NBLK, 128>>>();
    k_combine<<<1, 64>>>(out);
}